// round 2
// baseline (speedup 1.0000x reference)
#include <cuda_runtime.h>
#include <math.h>

#define NN 131072          // nodes
#define EE 2097152         // edges
#define BB 64              // graphs
#define NPG 2048
#define KTOP 30
#define FULLMASK 0xffffffffu

// ---------------- scratch (static device globals; no allocation) ----------------
__device__ int   g_rowstart[NN];
__device__ int   g_cursor[NN];
__device__ int   g_blocksums[128];
__device__ int   g_csr_col[EE];
__device__ int   g_csr_eid[EE];
__device__ float g_z[NN * 32];
__device__ float g_z2[NN * 32];
__device__ float g_h0[NN * 32];
__device__ float g_h1[NN * 32];
__device__ float g_h2[NN * 32];
__device__ float g_z3[NN];
__device__ float g_h3[NN];
__device__ int   g_topk[BB * KTOP];

// ---------------- CSR build: prefix scan of degrees ----------------
__global__ void k_scan1(const float* __restrict__ degs) {
    __shared__ int tmp[1024];
    int t = threadIdx.x;
    int idx = blockIdx.x * 1024 + t;
    int c = (int)(degs[idx] + 0.5f) - 1;       // node_degs = count + 1
    tmp[t] = c;
    __syncthreads();
    for (int off = 1; off < 1024; off <<= 1) {
        int v = (t >= off) ? tmp[t - off] : 0;
        __syncthreads();
        tmp[t] += v;
        __syncthreads();
    }
    g_rowstart[idx] = tmp[t] - c;              // exclusive within block
    if (t == 1023) g_blocksums[blockIdx.x] = tmp[t];
}

__global__ void k_scan2() {
    __shared__ int tmp[128];
    int t = threadIdx.x;
    int c = g_blocksums[t];
    tmp[t] = c;
    __syncthreads();
    for (int off = 1; off < 128; off <<= 1) {
        int v = (t >= off) ? tmp[t - off] : 0;
        __syncthreads();
        tmp[t] += v;
        __syncthreads();
    }
    g_blocksums[t] = tmp[t] - c;               // exclusive
}

__global__ void k_scan3() {
    int t = threadIdx.x;
    int idx = blockIdx.x * 1024 + t;
    int v = g_rowstart[idx] + g_blocksums[blockIdx.x];
    g_rowstart[idx] = v;
    g_cursor[idx]   = v;
}

__global__ void k_fill(const int* __restrict__ erow, const int* __restrict__ ecol) {
    int e = blockIdx.x * 256 + threadIdx.x;
    int r = erow[e];
    int p = atomicAdd(&g_cursor[r], 1);
    g_csr_col[p] = ecol[e];
    g_csr_eid[p] = e;
}

// ---------------- fused e2n gather + z0 = concat(nf, e2n) @ W0^T ----------------
__global__ void k_z0(const float* __restrict__ nodef, const float* __restrict__ edgef,
                     const float* __restrict__ degs, const float* __restrict__ W0) {
    __shared__ float sW[160 * 32];             // transposed: sW[i*32+c] = W0[c,i]
    int t = threadIdx.x;
    for (int s = t; s < 160 * 32; s += 256) {
        int i = s >> 5, c = s & 31;
        sW[i * 32 + c] = W0[c * 160 + i];
    }
    __syncthreads();
    int warp = (blockIdx.x * 256 + t) >> 5;
    int lane = t & 31;
    int v = warp;
    int cnt = (int)(degs[v] + 0.5f) - 1;
    int start = g_rowstart[v];

    // e2n: sum edge features (lane = channel, coalesced 128B per edge)
    float acc = 0.f;
    for (int kb = 0; kb < cnt; kb += 32) {
        int m = min(32, cnt - kb);
        int eid = (lane < m) ? g_csr_eid[start + kb + lane] : 0;
        for (int k = 0; k < m; k++) {
            int e = __shfl_sync(FULLMASK, eid, k);
            acc += edgef[e * 32 + lane];
        }
    }
    // z0[c] = sum_i W0[c,i] * h[i];  h = [node_feat(128) | e2n(32)]
    float z = 0.f;
    const float* nf = nodef + v * 128;
    for (int base = 0; base < 128; base += 32) {
        float val = nf[base + lane];
#pragma unroll
        for (int j = 0; j < 32; j++) {
            float bv = __shfl_sync(FULLMASK, val, j);
            z += sW[(base + j) * 32 + lane] * bv;
        }
    }
#pragma unroll
    for (int j = 0; j < 32; j++) {
        float bv = __shfl_sync(FULLMASK, acc, j);
        z += sW[(128 + j) * 32 + lane] * bv;
    }
    g_z[v * 32 + lane] = z;
}

// ---------------- GNN layer: pooled = z[v] + sum z[col]; h = tanh((pooled+b)/deg);
//                  z_next = h @ Wn^T.  Buffer routing is compile-time (STAGE). ----
template <int STAGE>
__global__ void k_layer(const float* __restrict__ bias, const float* __restrict__ degs,
                        const float* __restrict__ Wn) {
    const float* zin  = (STAGE == 1) ? g_z2 : g_z;
    float* hout = (STAGE == 0) ? g_h0 : (STAGE == 1) ? g_h1 : g_h2;
    constexpr int NCOLS = (STAGE == 2) ? 1 : 32;

    __shared__ float sWt[32 * 32];
    int t = threadIdx.x;
    if (NCOLS == 32) {
        for (int s = t; s < 1024; s += 256) {
            int c = s >> 5, j = s & 31;
            sWt[j * 32 + c] = Wn[c * 32 + j];
        }
    } else {
        if (t < 32) sWt[t] = Wn[t];
    }
    __syncthreads();
    int warp = (blockIdx.x * 256 + t) >> 5;
    int lane = t & 31;
    int v = warp;
    float deg = degs[v];
    int cnt = (int)(deg + 0.5f) - 1;
    int start = g_rowstart[v];

    float p = zin[v * 32 + lane];
    for (int kb = 0; kb < cnt; kb += 32) {
        int m = min(32, cnt - kb);
        int col = (lane < m) ? g_csr_col[start + kb + lane] : 0;
        for (int k = 0; k < m; k++) {
            int c2 = __shfl_sync(FULLMASK, col, k);
            p += zin[c2 * 32 + lane];
        }
    }
    float h = tanhf((p + bias[lane]) / deg);
    hout[v * 32 + lane] = h;

    if (NCOLS == 32) {
        float z2 = 0.f;
#pragma unroll
        for (int j = 0; j < 32; j++) {
            float hv = __shfl_sync(FULLMASK, h, j);
            z2 += sWt[j * 32 + lane] * hv;
        }
        float* zout = (STAGE == 0) ? g_z2 : g_z;
        zout[v * 32 + lane] = z2;
    } else {
        float part = sWt[lane] * h;
#pragma unroll
        for (int o = 16; o; o >>= 1) part += __shfl_xor_sync(FULLMASK, part, o);
        if (lane == 0) g_z3[v] = part;
    }
}

// ---------------- layer 3 (scalar channel) ----------------
__global__ void k_layer3(const float* __restrict__ degs, const float* __restrict__ b3) {
    int t = threadIdx.x;
    int warp = (blockIdx.x * 256 + t) >> 5;
    int lane = t & 31;
    int v = warp;
    float deg = degs[v];
    int cnt = (int)(deg + 0.5f) - 1;
    int start = g_rowstart[v];
    float s = 0.f;
    for (int k = lane; k < cnt; k += 32) s += g_z3[g_csr_col[start + k]];
#pragma unroll
    for (int o = 16; o; o >>= 1) s += __shfl_xor_sync(FULLMASK, s, o);
    if (lane == 0) {
        float pooled = s + g_z3[v];
        g_h3[v] = tanhf((pooled + b3[0]) / deg);
    }
}

// ---------------- sortpool: top-K per graph by h3, JAX tie semantics ----------------
__global__ void k_topk() {
    int b = blockIdx.x;
    int t = threadIdx.x;                       // 256 threads
    __shared__ float sv[NPG];
    __shared__ float rv[256];
    __shared__ int   ri[256];
    for (int i = t; i < NPG; i += 256) sv[i] = g_h3[b * NPG + i];
    __syncthreads();
    for (int r = 0; r < KTOP; r++) {
        float bv = -3.0f;                      // tanh in (-1,1); removed entries = -2
        int bi = NPG;
        for (int i = t; i < NPG; i += 256) {
            float v = sv[i];
            if (v > bv || (v == bv && i < bi)) { bv = v; bi = i; }
        }
        rv[t] = bv; ri[t] = bi;
        __syncthreads();
        for (int o = 128; o > 0; o >>= 1) {
            if (t < o) {
                float v2 = rv[t + o]; int i2 = ri[t + o];
                if (v2 > rv[t] || (v2 == rv[t] && i2 < ri[t])) { rv[t] = v2; ri[t] = i2; }
            }
            __syncthreads();
        }
        if (t == 0) { g_topk[b * KTOP + r] = ri[0]; sv[ri[0]] = -2.0f; }
        __syncthreads();
    }
}

// ---------------- CNN head + MLP + log_softmax, one block per graph ----------------
__global__ void k_classify(const float* __restrict__ Wc1, const float* __restrict__ bc1,
                           const float* __restrict__ Wc2, const float* __restrict__ bc2,
                           const float* __restrict__ Wh,  const float* __restrict__ bh,
                           const float* __restrict__ Wo,  const float* __restrict__ bo,
                           float* __restrict__ out) {
    int b = blockIdx.x, t = threadIdx.x;       // 128 threads
    __shared__ float pg[KTOP * 97];
    __shared__ float y[16 * 30];
    __shared__ float mp[16 * 15];
    __shared__ float dd[352];
    __shared__ float hh[128];
    __shared__ float lg[10];
    __shared__ float lse;

    for (int s = t; s < KTOP * 97; s += 128) {
        int k = s / 97, d = s % 97;
        int node = g_topk[b * KTOP + k] + b * NPG;
        float v;
        if (d < 32)      v = g_h0[node * 32 + d];
        else if (d < 64) v = g_h1[node * 32 + (d - 32)];
        else if (d < 96) v = g_h2[node * 32 + (d - 64)];
        else             v = g_h3[node];
        pg[k * 97 + d] = v;
    }
    __syncthreads();
    // conv1d(1->16, kernel=stride=97) == per-node linear; relu
    for (int s = t; s < 480; s += 128) {
        int c = s / 30, k = s % 30;
        float acc = bc1[c];
        for (int d = 0; d < 97; d++) acc += Wc1[c * 97 + d] * pg[k * 97 + d];
        y[c * 30 + k] = fmaxf(acc, 0.f);
    }
    __syncthreads();
    for (int s = t; s < 240; s += 128) {
        int c = s / 15, p = s % 15;
        mp[c * 15 + p] = fmaxf(y[c * 30 + 2 * p], y[c * 30 + 2 * p + 1]);
    }
    __syncthreads();
    // conv1d 16->32, kernel 5, valid; relu  (relu(relu)=relu for the dense input)
    for (int s = t; s < 352; s += 128) {
        int o = s / 11, p = s % 11;
        float acc = bc2[o];
        for (int c = 0; c < 16; c++) {
#pragma unroll
            for (int kk = 0; kk < 5; kk++)
                acc += Wc2[(o * 16 + c) * 5 + kk] * mp[c * 15 + p + kk];
        }
        dd[o * 11 + p] = fmaxf(acc, 0.f);
    }
    __syncthreads();
    {
        float acc = bh[t];
        for (int d = 0; d < 352; d++) acc += Wh[t * 352 + d] * dd[d];
        hh[t] = fmaxf(acc, 0.f);
    }
    __syncthreads();
    if (t < 10) {
        float acc = bo[t];
        for (int j = 0; j < 128; j++) acc += Wo[t * 128 + j] * hh[j];
        lg[t] = acc;
    }
    __syncthreads();
    if (t == 0) {
        float m = lg[0];
        for (int i = 1; i < 10; i++) m = fmaxf(m, lg[i]);
        float s = 0.f;
        for (int i = 0; i < 10; i++) s += expf(lg[i] - m);
        lse = m + logf(s);
    }
    __syncthreads();
    if (t < 10) out[b * 10 + t] = lg[t] - lse;
}

// ---------------- launch: kernel launches ONLY ----------------
extern "C" void kernel_launch(void* const* d_in, const int* in_sizes, int n_in,
                              void* d_out, int out_size) {
    const float* node_feat = (const float*)d_in[0];
    const float* edge_feat = (const float*)d_in[1];
    const float* node_degs = (const float*)d_in[2];
    const float* W0 = (const float*)d_in[3];
    const float* b0 = (const float*)d_in[4];
    const float* W1 = (const float*)d_in[5];
    const float* b1 = (const float*)d_in[6];
    const float* W2 = (const float*)d_in[7];
    const float* b2 = (const float*)d_in[8];
    const float* W3 = (const float*)d_in[9];
    const float* b3 = (const float*)d_in[10];
    const float* Wc1 = (const float*)d_in[11];
    const float* bc1 = (const float*)d_in[12];
    const float* Wc2 = (const float*)d_in[13];
    const float* bc2 = (const float*)d_in[14];
    const float* Wh = (const float*)d_in[15];
    const float* bh = (const float*)d_in[16];
    const float* Wo = (const float*)d_in[17];
    const float* bo = (const float*)d_in[18];
    const int* edge_row = (const int*)d_in[19];
    const int* edge_col = (const int*)d_in[20];
    float* out = (float*)d_out;

    // CSR build
    k_scan1<<<128, 1024>>>(node_degs);
    k_scan2<<<1, 128>>>();
    k_scan3<<<128, 1024>>>();
    k_fill<<<EE / 256, 256>>>(edge_row, edge_col);

    // fused e2n + z0
    k_z0<<<NN / 8, 256>>>(node_feat, edge_feat, node_degs, W0);

    // layers: z0->h0,z1 ; z1->h1,z2 ; z2->h2,z3 ; z3->h3
    k_layer<0><<<NN / 8, 256>>>(b0, node_degs, W1);
    k_layer<1><<<NN / 8, 256>>>(b1, node_degs, W2);
    k_layer<2><<<NN / 8, 256>>>(b2, node_degs, W3);
    k_layer3<<<NN / 8, 256>>>(node_degs, b3);

    // sortpool + head
    k_topk<<<BB, 256>>>();
    k_classify<<<BB, 128>>>(Wc1, bc1, Wc2, bc2, Wh, bh, Wo, bo, out);
}

// round 5
// speedup vs baseline: 1.0001x; 1.0001x over previous
#include <cuda_runtime.h>
#include <math.h>

#define NN 131072          // nodes
#define EE 2097152         // edges
#define BB 64              // graphs
#define NPG 2048
#define KTOP 30
#define FULLMASK 0xffffffffu

// ---------------- scratch (static device globals; no allocation) ----------------
__device__ int   g_rowstart[NN];
__device__ int   g_cursor[NN];
__device__ int   g_blocksums[128];
__device__ int2  g_csr[EE];        // .x = col, .y = eid  (one 8B store per edge)
__device__ float g_z[NN * 32];
__device__ float g_z2[NN * 32];
__device__ float g_h0[NN * 32];
__device__ float g_h1[NN * 32];
__device__ float g_h2[NN * 32];
__device__ float g_z3[NN];
__device__ float g_h3[NN];
__device__ int   g_topk[BB * KTOP];

// ---------------- CSR build: prefix scan of degrees ----------------
__global__ void k_scan1(const float* __restrict__ degs) {
    __shared__ int tmp[1024];
    int t = threadIdx.x;
    int idx = blockIdx.x * 1024 + t;
    int c = (int)(degs[idx] + 0.5f) - 1;       // node_degs = count + 1
    tmp[t] = c;
    __syncthreads();
    for (int off = 1; off < 1024; off <<= 1) {
        int v = (t >= off) ? tmp[t - off] : 0;
        __syncthreads();
        tmp[t] += v;
        __syncthreads();
    }
    g_rowstart[idx] = tmp[t] - c;              // exclusive within block
    if (t == 1023) g_blocksums[blockIdx.x] = tmp[t];
}

__global__ void k_scan2() {
    __shared__ int tmp[128];
    int t = threadIdx.x;
    int c = g_blocksums[t];
    tmp[t] = c;
    __syncthreads();
    for (int off = 1; off < 128; off <<= 1) {
        int v = (t >= off) ? tmp[t - off] : 0;
        __syncthreads();
        tmp[t] += v;
        __syncthreads();
    }
    g_blocksums[t] = tmp[t] - c;               // exclusive
}

__global__ void k_scan3() {
    int t = threadIdx.x;
    int idx = blockIdx.x * 1024 + t;
    int v = g_rowstart[idx] + g_blocksums[blockIdx.x];
    g_rowstart[idx] = v;
    g_cursor[idx]   = v;
}

__global__ void k_fill(const int* __restrict__ erow, const int* __restrict__ ecol) {
    int e = blockIdx.x * 256 + threadIdx.x;
    int r = erow[e];
    int p = atomicAdd(&g_cursor[r], 1);
    g_csr[p] = make_int2(ecol[e], e);          // single 8B scattered store
}

// ---------------- fused e2n gather + z0 = concat(nf, e2n) @ W0^T ----------------
// MLP fix: 8 independent accumulators -> 8 LDGs in flight per warp.
__global__ void k_z0(const float* __restrict__ nodef, const float* __restrict__ edgef,
                     const float* __restrict__ degs, const float* __restrict__ W0) {
    __shared__ float sW[160 * 32];             // transposed: sW[i*32+c] = W0[c,i]
    int t = threadIdx.x;
    for (int s = t; s < 160 * 32; s += 256) {
        int i = s >> 5, c = s & 31;
        sW[i * 32 + c] = W0[c * 160 + i];
    }
    __syncthreads();
    int warp = (blockIdx.x * 256 + t) >> 5;
    int lane = t & 31;
    int v = warp;
    int cnt = (int)(degs[v] + 0.5f) - 1;
    int start = g_rowstart[v];

    // e2n: sum edge features (lane = channel, coalesced 128B per edge)
    float a0 = 0.f, a1 = 0.f, a2 = 0.f, a3 = 0.f;
    float a4 = 0.f, a5 = 0.f, a6 = 0.f, a7 = 0.f;
    for (int kb = 0; kb < cnt; kb += 32) {
        int m = min(32, cnt - kb);
        int eid = (lane < m) ? g_csr[start + kb + lane].y : 0;
        int k = 0;
        for (; k + 8 <= m; k += 8) {
            int e0 = __shfl_sync(FULLMASK, eid, k);
            int e1 = __shfl_sync(FULLMASK, eid, k + 1);
            int e2 = __shfl_sync(FULLMASK, eid, k + 2);
            int e3 = __shfl_sync(FULLMASK, eid, k + 3);
            int e4 = __shfl_sync(FULLMASK, eid, k + 4);
            int e5 = __shfl_sync(FULLMASK, eid, k + 5);
            int e6 = __shfl_sync(FULLMASK, eid, k + 6);
            int e7 = __shfl_sync(FULLMASK, eid, k + 7);
            a0 += edgef[e0 * 32 + lane];
            a1 += edgef[e1 * 32 + lane];
            a2 += edgef[e2 * 32 + lane];
            a3 += edgef[e3 * 32 + lane];
            a4 += edgef[e4 * 32 + lane];
            a5 += edgef[e5 * 32 + lane];
            a6 += edgef[e6 * 32 + lane];
            a7 += edgef[e7 * 32 + lane];
        }
        for (; k + 2 <= m; k += 2) {
            int e0 = __shfl_sync(FULLMASK, eid, k);
            int e1 = __shfl_sync(FULLMASK, eid, k + 1);
            a0 += edgef[e0 * 32 + lane];
            a1 += edgef[e1 * 32 + lane];
        }
        if (k < m) {
            int e0 = __shfl_sync(FULLMASK, eid, k);
            a0 += edgef[e0 * 32 + lane];
        }
    }
    float acc = ((a0 + a1) + (a2 + a3)) + ((a4 + a5) + (a6 + a7));

    // z0[c] = sum_i W0[c,i] * h[i];  h = [node_feat(128) | e2n(32)]
    float z = 0.f;
    const float* nf = nodef + v * 128;
    for (int base = 0; base < 128; base += 32) {
        float val = nf[base + lane];
#pragma unroll
        for (int j = 0; j < 32; j++) {
            float bv = __shfl_sync(FULLMASK, val, j);
            z += sW[(base + j) * 32 + lane] * bv;
        }
    }
#pragma unroll
    for (int j = 0; j < 32; j++) {
        float bv = __shfl_sync(FULLMASK, acc, j);
        z += sW[(128 + j) * 32 + lane] * bv;
    }
    g_z[v * 32 + lane] = z;
}

// ---------------- GNN layer: pooled = z[v] + sum z[col]; h = tanh((pooled+b)/deg);
//                  z_next = h @ Wn^T.  Buffer routing is compile-time (STAGE). ----
template <int STAGE>
__global__ void k_layer(const float* __restrict__ bias, const float* __restrict__ degs,
                        const float* __restrict__ Wn) {
    const float* zin  = (STAGE == 1) ? g_z2 : g_z;
    float* hout = (STAGE == 0) ? g_h0 : (STAGE == 1) ? g_h1 : g_h2;
    constexpr int NCOLS = (STAGE == 2) ? 1 : 32;

    __shared__ float sWt[32 * 32];
    int t = threadIdx.x;
    if (NCOLS == 32) {
        for (int s = t; s < 1024; s += 256) {
            int c = s >> 5, j = s & 31;
            sWt[j * 32 + c] = Wn[c * 32 + j];
        }
    } else {
        if (t < 32) sWt[t] = Wn[t];
    }
    __syncthreads();
    int warp = (blockIdx.x * 256 + t) >> 5;
    int lane = t & 31;
    int v = warp;
    float deg = degs[v];
    int cnt = (int)(deg + 0.5f) - 1;
    int start = g_rowstart[v];

    float p0 = zin[v * 32 + lane], p1 = 0.f, p2 = 0.f, p3 = 0.f;
    for (int kb = 0; kb < cnt; kb += 32) {
        int m = min(32, cnt - kb);
        int col = (lane < m) ? g_csr[start + kb + lane].x : 0;
        int k = 0;
        for (; k + 4 <= m; k += 4) {
            int c0 = __shfl_sync(FULLMASK, col, k);
            int c1 = __shfl_sync(FULLMASK, col, k + 1);
            int c2 = __shfl_sync(FULLMASK, col, k + 2);
            int c3 = __shfl_sync(FULLMASK, col, k + 3);
            p0 += zin[c0 * 32 + lane];
            p1 += zin[c1 * 32 + lane];
            p2 += zin[c2 * 32 + lane];
            p3 += zin[c3 * 32 + lane];
        }
        for (; k < m; k++) {
            int c2x = __shfl_sync(FULLMASK, col, k);
            p0 += zin[c2x * 32 + lane];
        }
    }
    float p = (p0 + p1) + (p2 + p3);
    float h = tanhf((p + bias[lane]) / deg);
    hout[v * 32 + lane] = h;

    if (NCOLS == 32) {
        float z2 = 0.f;
#pragma unroll
        for (int j = 0; j < 32; j++) {
            float hv = __shfl_sync(FULLMASK, h, j);
            z2 += sWt[j * 32 + lane] * hv;
        }
        float* zout = (STAGE == 0) ? g_z2 : g_z;
        zout[v * 32 + lane] = z2;
    } else {
        float part = sWt[lane] * h;
#pragma unroll
        for (int o = 16; o; o >>= 1) part += __shfl_xor_sync(FULLMASK, part, o);
        if (lane == 0) g_z3[v] = part;
    }
}

// ---------------- layer 3 (scalar channel) ----------------
__global__ void k_layer3(const float* __restrict__ degs, const float* __restrict__ b3) {
    int t = threadIdx.x;
    int warp = (blockIdx.x * 256 + t) >> 5;
    int lane = t & 31;
    int v = warp;
    float deg = degs[v];
    int cnt = (int)(deg + 0.5f) - 1;
    int start = g_rowstart[v];
    float s = 0.f;
    for (int k = lane; k < cnt; k += 32) s += g_z3[g_csr[start + k].x];
#pragma unroll
    for (int o = 16; o; o >>= 1) s += __shfl_xor_sync(FULLMASK, s, o);
    if (lane == 0) {
        float pooled = s + g_z3[v];
        g_h3[v] = tanhf((pooled + b3[0]) / deg);
    }
}

// ---------------- sortpool: top-K per graph by h3, JAX tie semantics ----------------
__global__ void k_topk() {
    int b = blockIdx.x;
    int t = threadIdx.x;                       // 256 threads
    __shared__ float sv[NPG];
    __shared__ float rv[256];
    __shared__ int   ri[256];
    for (int i = t; i < NPG; i += 256) sv[i] = g_h3[b * NPG + i];
    __syncthreads();
    for (int r = 0; r < KTOP; r++) {
        float bv = -3.0f;                      // tanh in (-1,1); removed entries = -2
        int bi = NPG;
        for (int i = t; i < NPG; i += 256) {
            float v = sv[i];
            if (v > bv || (v == bv && i < bi)) { bv = v; bi = i; }
        }
        rv[t] = bv; ri[t] = bi;
        __syncthreads();
        for (int o = 128; o > 0; o >>= 1) {
            if (t < o) {
                float v2 = rv[t + o]; int i2 = ri[t + o];
                if (v2 > rv[t] || (v2 == rv[t] && i2 < ri[t])) { rv[t] = v2; ri[t] = i2; }
            }
            __syncthreads();
        }
        if (t == 0) { g_topk[b * KTOP + r] = ri[0]; sv[ri[0]] = -2.0f; }
        __syncthreads();
    }
}

// ---------------- CNN head + MLP + log_softmax, one block per graph ----------------
__global__ void k_classify(const float* __restrict__ Wc1, const float* __restrict__ bc1,
                           const float* __restrict__ Wc2, const float* __restrict__ bc2,
                           const float* __restrict__ Wh,  const float* __restrict__ bh,
                           const float* __restrict__ Wo,  const float* __restrict__ bo,
                           float* __restrict__ out) {
    int b = blockIdx.x, t = threadIdx.x;       // 128 threads
    __shared__ float pg[KTOP * 97];
    __shared__ float y[16 * 30];
    __shared__ float mp[16 * 15];
    __shared__ float dd[352];
    __shared__ float hh[128];
    __shared__ float lg[10];
    __shared__ float lse;

    for (int s = t; s < KTOP * 97; s += 128) {
        int k = s / 97, d = s % 97;
        int node = g_topk[b * KTOP + k] + b * NPG;
        float v;
        if (d < 32)      v = g_h0[node * 32 + d];
        else if (d < 64) v = g_h1[node * 32 + (d - 32)];
        else if (d < 96) v = g_h2[node * 32 + (d - 64)];
        else             v = g_h3[node];
        pg[k * 97 + d] = v;
    }
    __syncthreads();
    // conv1d(1->16, kernel=stride=97) == per-node linear; relu
    for (int s = t; s < 480; s += 128) {
        int c = s / 30, k = s % 30;
        float acc = bc1[c];
        for (int d = 0; d < 97; d++) acc += Wc1[c * 97 + d] * pg[k * 97 + d];
        y[c * 30 + k] = fmaxf(acc, 0.f);
    }
    __syncthreads();
    for (int s = t; s < 240; s += 128) {
        int c = s / 15, p = s % 15;
        mp[c * 15 + p] = fmaxf(y[c * 30 + 2 * p], y[c * 30 + 2 * p + 1]);
    }
    __syncthreads();
    // conv1d 16->32, kernel 5, valid; relu  (relu(relu)=relu for the dense input)
    for (int s = t; s < 352; s += 128) {
        int o = s / 11, p = s % 11;
        float acc = bc2[o];
        for (int c = 0; c < 16; c++) {
#pragma unroll
            for (int kk = 0; kk < 5; kk++)
                acc += Wc2[(o * 16 + c) * 5 + kk] * mp[c * 15 + p + kk];
        }
        dd[o * 11 + p] = fmaxf(acc, 0.f);
    }
    __syncthreads();
    {
        float acc = bh[t];
        for (int d = 0; d < 352; d++) acc += Wh[t * 352 + d] * dd[d];
        hh[t] = fmaxf(acc, 0.f);
    }
    __syncthreads();
    if (t < 10) {
        float acc = bo[t];
        for (int j = 0; j < 128; j++) acc += Wo[t * 128 + j] * hh[j];
        lg[t] = acc;
    }
    __syncthreads();
    if (t == 0) {
        float m = lg[0];
        for (int i = 1; i < 10; i++) m = fmaxf(m, lg[i]);
        float s = 0.f;
        for (int i = 0; i < 10; i++) s += expf(lg[i] - m);
        lse = m + logf(s);
    }
    __syncthreads();
    if (t < 10) out[b * 10 + t] = lg[t] - lse;
}

// ---------------- launch: kernel launches ONLY ----------------
extern "C" void kernel_launch(void* const* d_in, const int* in_sizes, int n_in,
                              void* d_out, int out_size) {
    const float* node_feat = (const float*)d_in[0];
    const float* edge_feat = (const float*)d_in[1];
    const float* node_degs = (const float*)d_in[2];
    const float* W0 = (const float*)d_in[3];
    const float* b0 = (const float*)d_in[4];
    const float* W1 = (const float*)d_in[5];
    const float* b1 = (const float*)d_in[6];
    const float* W2 = (const float*)d_in[7];
    const float* b2 = (const float*)d_in[8];
    const float* W3 = (const float*)d_in[9];
    const float* b3 = (const float*)d_in[10];
    const float* Wc1 = (const float*)d_in[11];
    const float* bc1 = (const float*)d_in[12];
    const float* Wc2 = (const float*)d_in[13];
    const float* bc2 = (const float*)d_in[14];
    const float* Wh = (const float*)d_in[15];
    const float* bh = (const float*)d_in[16];
    const float* Wo = (const float*)d_in[17];
    const float* bo = (const float*)d_in[18];
    const int* edge_row = (const int*)d_in[19];
    const int* edge_col = (const int*)d_in[20];
    float* out = (float*)d_out;

    // CSR build
    k_scan1<<<128, 1024>>>(node_degs);
    k_scan2<<<1, 128>>>();
    k_scan3<<<128, 1024>>>();
    k_fill<<<EE / 256, 256>>>(edge_row, edge_col);

    // fused e2n + z0
    k_z0<<<NN / 8, 256>>>(node_feat, edge_feat, node_degs, W0);

    // layers: z0->h0,z1 ; z1->h1,z2 ; z2->h2,z3 ; z3->h3
    k_layer<0><<<NN / 8, 256>>>(b0, node_degs, W1);
    k_layer<1><<<NN / 8, 256>>>(b1, node_degs, W2);
    k_layer<2><<<NN / 8, 256>>>(b2, node_degs, W3);
    k_layer3<<<NN / 8, 256>>>(node_degs, b3);

    // sortpool + head
    k_topk<<<BB, 256>>>();
    k_classify<<<BB, 128>>>(Wc1, bc1, Wc2, bc2, Wh, bh, Wo, bo, out);
}